// round 11
// baseline (speedup 1.0000x reference)
#include <cuda_runtime.h>
#include <cuda_fp16.h>
#include <mma.h>
#include <cstdint>

using namespace nvcuda;

#define D 64
#define MAXN 100000
#define MAXNP 100096           // padded so last tile's wmma A-loads stay in-bounds
#define MAXE 1600000
#define TILE 128
#define EPI_LD 68              // epilogue smem row stride (floats)

// ---------------- static scratch (no allocation allowed) -------------------
__device__ __half g_meanh[(size_t)MAXNP * D];
__device__ __half g_meanl[(size_t)MAXNP * D];
__device__ __half g_xh[(size_t)MAXNP * D];    // hi of gather/self operand
__device__ __half g_xl[(size_t)MAXNP * D];    // lo residual
__device__ __half g_w16[2 * 4 * 4096];        // per layer: wl_hi, wl_lo, wr_hi, wr_lo
__device__ int    g_deg[MAXN];
__device__ int    g_rowptr[MAXN];
__device__ int    g_cursor[MAXN];
__device__ int    g_csrsrc[MAXE + 8];         // +8: unpredicated batch idx loads
__device__ int    g_blocksums[128];
__device__ int    g_blockoffs[128];

// ---------------- CSR build ------------------------------------------------
__global__ void count_kernel(const int* __restrict__ dst, int* __restrict__ deg,
                             int n_edges) {
    int e = blockIdx.x * blockDim.x + threadIdx.x;
    if (e < n_edges) atomicAdd(deg + __ldg(dst + e), 1);
}

__global__ void scan_kernel(const int* __restrict__ in, int* __restrict__ out,
                            int* sums, int n) {
    __shared__ int sm[1024];
    int t = threadIdx.x;
    int i = blockIdx.x * 1024 + t;
    int v = (i < n) ? in[i] : 0;
    sm[t] = v;
    __syncthreads();
#pragma unroll
    for (int off = 1; off < 1024; off <<= 1) {
        int add = (t >= off) ? sm[t - off] : 0;
        __syncthreads();
        sm[t] += add;
        __syncthreads();
    }
    if (i < n) out[i] = sm[t] - v;
    if (sums != nullptr && t == 1023) sums[blockIdx.x] = sm[1023];
}

__global__ void add_off_kernel(int* __restrict__ rowptr, int* __restrict__ cursor,
                               const int* __restrict__ boffs, int n) {
    int i = blockIdx.x * blockDim.x + threadIdx.x;
    if (i < n) {
        int v = rowptr[i] + boffs[i >> 10];
        rowptr[i] = v;
        cursor[i] = v;
    }
}

__global__ void fill_kernel(const int* __restrict__ src, const int* __restrict__ dst,
                            int* __restrict__ cursor, int* __restrict__ csr,
                            int n_edges) {
    int e = blockIdx.x * blockDim.x + threadIdx.x;
    if (e < n_edges) {
        int d = __ldg(dst + e);
        int pos = atomicAdd(cursor + d, 1);
        csr[pos] = __ldg(src + e);
    }
}

// ---------------- fp32 -> fp16 hi/lo conversion (x) --------------------------
__global__ void convert_kernel(const float4* __restrict__ in,
                               uint2* __restrict__ outh,
                               uint2* __restrict__ outl, int n4) {
    int i = blockIdx.x * blockDim.x + threadIdx.x;
    if (i < n4) {
        float4 v = __ldg(in + i);
        __half2 h0 = __floats2half2_rn(v.x, v.y);
        __half2 h1 = __floats2half2_rn(v.z, v.w);
        float2 f0 = __half22float2(h0);
        float2 f1 = __half22float2(h1);
        __half2 l0 = __floats2half2_rn(v.x - f0.x, v.y - f0.y);
        __half2 l1 = __floats2half2_rn(v.z - f1.x, v.w - f1.y);
        outh[i] = make_uint2(*(unsigned*)&h0, *(unsigned*)&h1);
        outl[i] = make_uint2(*(unsigned*)&l0, *(unsigned*)&l1);
    }
}

// ---------------- weight hi/lo split (both layers) ---------------------------
__global__ void wsplit_kernel(const float* __restrict__ W1l,
                              const float* __restrict__ W1r,
                              const float* __restrict__ W2l,
                              const float* __restrict__ W2r,
                              __half* __restrict__ w16) {
    int i = blockIdx.x * blockDim.x + threadIdx.x;
    if (i >= 4096) return;
    const float* srcs[4] = {W1l, W1r, W2l, W2r};
#pragma unroll
    for (int l = 0; l < 2; l++) {
#pragma unroll
        for (int m = 0; m < 2; m++) {
            float v = __ldg(srcs[l * 2 + m] + i);
            __half hi = __float2half_rn(v);
            __half lo = __float2half_rn(v - __half2float(hi));
            w16[((size_t)l * 4 + m * 2 + 0) * 4096 + i] = hi;
            w16[((size_t)l * 4 + m * 2 + 1) * 4096 + i] = lo;
        }
    }
}

// ---------------- aggregate: fp16 gather, fully predicated batches ----------
// 2 nodes/warp. Index batches load UNPREDICATED (csr padded), row loads
// predicated -> MLP stays 8 through the final partial batch (no scalar tail).
__global__ void aggregate_kernel(const uint2* __restrict__ xh2,
                                 const int* __restrict__ csr,
                                 const int* __restrict__ rowptr,
                                 const int* __restrict__ deg,
                                 __half* __restrict__ mh,
                                 __half* __restrict__ ml, int n_nodes) {
    int warp = (blockIdx.x * blockDim.x + threadIdx.x) >> 5;
    int n0 = warp * 2;
    if (n0 >= n_nodes) return;
    int lane = threadIdx.x & 31;
    int half_ = lane >> 4;
    int q = lane & 15;
    int node = n0 + half_;
    bool valid = node < n_nodes;

    int base = valid ? __ldg(rowptr + node) : 0;
    int dg   = valid ? __ldg(deg + node) : 0;
    int dgA = __shfl_sync(0xffffffffu, dg, 0);
    int dgB = __shfl_sync(0xffffffffu, dg, 16);
    int maxdg = max(dgA, dgB);

    float a0 = 0.f, a1 = 0.f, a2 = 0.f, a3 = 0.f;

    for (int j = 0; j < maxdg; j += 8) {
        int idx[8];
#pragma unroll
        for (int i = 0; i < 8; i++)
            idx[i] = __ldg(csr + base + j + i);      // padded: always in-bounds
#pragma unroll
        for (int i = 0; i < 8; i++) {
            if (j + i < dg) {
                uint2 v = __ldg(xh2 + (size_t)idx[i] * 16 + q);
                float2 f0 = __half22float2(*(__half2*)&v.x);
                float2 f1 = __half22float2(*(__half2*)&v.y);
                a0 += f0.x; a1 += f0.y; a2 += f1.x; a3 += f1.y;
            }
        }
    }

    float inv = 1.0f / fmaxf((float)dg, 1.0f);
    a0 *= inv; a1 *= inv; a2 *= inv; a3 *= inv;
    if (valid) {
        __half2 h0 = __floats2half2_rn(a0, a1);
        __half2 h1 = __floats2half2_rn(a2, a3);
        float2 f0 = __half22float2(h0);
        float2 f1 = __half22float2(h1);
        __half2 l0 = __floats2half2_rn(a0 - f0.x, a1 - f0.y);
        __half2 l1 = __floats2half2_rn(a2 - f1.x, a3 - f1.y);
        *(uint2*)(mh + (size_t)node * D + q * 4) =
            make_uint2(*(unsigned*)&h0, *(unsigned*)&h1);
        *(uint2*)(ml + (size_t)node * D + q * 4) =
            make_uint2(*(unsigned*)&l0, *(unsigned*)&l1);
    }
}

// ---------------- combine via wmma HMMA (R10 version) ------------------------
__global__ void __launch_bounds__(128)
combine_wmma(const __half* __restrict__ mh, const __half* __restrict__ ml,
             const __half* __restrict__ ah, const __half* __restrict__ al,
             const __half* __restrict__ w,     // wl_hi, wl_lo, wr_hi, wr_lo
             const float* __restrict__ bias,
             float* __restrict__ out32,        // layer 2 final (or null)
             __half* __restrict__ oh,          // layer 1 hi out (or null)
             __half* __restrict__ ol,          // layer 1 lo out (or null)
             int n_nodes, int do_relu) {
    extern __shared__ float epi[];            // [4][32][EPI_LD]
    int tid = threadIdx.x, wid = tid >> 5, lane = tid & 31;
    int rbase = blockIdx.x * TILE + wid * 32;

    wmma::fragment<wmma::accumulator, 16, 16, 16, float> acc[2][4];
#pragma unroll
    for (int mt = 0; mt < 2; mt++)
#pragma unroll
        for (int nt = 0; nt < 4; nt++) wmma::fill_fragment(acc[mt][nt], 0.0f);

#pragma unroll
    for (int k = 0; k < D; k += 16) {
        wmma::fragment<wmma::matrix_a, 16, 16, 16, __half, wmma::row_major>
            fmh[2], fml[2], fah[2], fal[2];
#pragma unroll
        for (int mt = 0; mt < 2; mt++) {
            size_t ab = (size_t)(rbase + mt * 16) * D + k;
            wmma::load_matrix_sync(fmh[mt], mh + ab, D);
            wmma::load_matrix_sync(fml[mt], ml + ab, D);
            wmma::load_matrix_sync(fah[mt], ah + ab, D);
            wmma::load_matrix_sync(fal[mt], al + ab, D);
        }
#pragma unroll
        for (int nt = 0; nt < 4; nt++) {
            size_t wb = (size_t)(nt * 16) * D + k;
            wmma::fragment<wmma::matrix_b, 16, 16, 16, __half, wmma::col_major>
                bwlh, bwll, bwrh, bwrl;
            wmma::load_matrix_sync(bwlh, w + 0 * 4096 + wb, D);
            wmma::load_matrix_sync(bwll, w + 1 * 4096 + wb, D);
            wmma::load_matrix_sync(bwrh, w + 2 * 4096 + wb, D);
            wmma::load_matrix_sync(bwrl, w + 3 * 4096 + wb, D);
#pragma unroll
            for (int mt = 0; mt < 2; mt++) {
                wmma::mma_sync(acc[mt][nt], fmh[mt], bwlh, acc[mt][nt]);
                wmma::mma_sync(acc[mt][nt], fml[mt], bwlh, acc[mt][nt]);
                wmma::mma_sync(acc[mt][nt], fmh[mt], bwll, acc[mt][nt]);
                wmma::mma_sync(acc[mt][nt], fah[mt], bwrh, acc[mt][nt]);
                wmma::mma_sync(acc[mt][nt], fal[mt], bwrh, acc[mt][nt]);
                wmma::mma_sync(acc[mt][nt], fah[mt], bwrl, acc[mt][nt]);
            }
        }
    }

    // epilogue: acc -> smem -> bias + relu -> coalesced stores
    float* ws = epi + (size_t)wid * 32 * EPI_LD;
#pragma unroll
    for (int mt = 0; mt < 2; mt++)
#pragma unroll
        for (int nt = 0; nt < 4; nt++)
            wmma::store_matrix_sync(ws + mt * 16 * EPI_LD + nt * 16,
                                    acc[mt][nt], EPI_LD, wmma::mem_row_major);
    __syncwarp();

    int q = lane & 15;
    int rh = lane >> 4;
    float4 b4 = __ldg((const float4*)bias + q);
#pragma unroll
    for (int it = 0; it < 16; it++) {
        int r = it * 2 + rh;
        float4 v = *(float4*)(ws + r * EPI_LD + q * 4);
        v.x += b4.x; v.y += b4.y; v.z += b4.z; v.w += b4.w;
        if (do_relu) {
            v.x = fmaxf(v.x, 0.f); v.y = fmaxf(v.y, 0.f);
            v.z = fmaxf(v.z, 0.f); v.w = fmaxf(v.w, 0.f);
        }
        int gm = rbase + r;
        if (gm < n_nodes) {
            if (out32) *(float4*)(out32 + (size_t)gm * D + q * 4) = v;
            if (oh) {
                __half2 h0 = __floats2half2_rn(v.x, v.y);
                __half2 h1 = __floats2half2_rn(v.z, v.w);
                float2 f0 = __half22float2(h0);
                float2 f1 = __half22float2(h1);
                __half2 l0 = __floats2half2_rn(v.x - f0.x, v.y - f0.y);
                __half2 l1 = __floats2half2_rn(v.z - f1.x, v.w - f1.y);
                *(uint2*)(oh + (size_t)gm * D + q * 4) =
                    make_uint2(*(unsigned*)&h0, *(unsigned*)&h1);
                *(uint2*)(ol + (size_t)gm * D + q * 4) =
                    make_uint2(*(unsigned*)&l0, *(unsigned*)&l1);
            }
        }
    }
}

// ---------------------------------------------------------------------------
extern "C" void kernel_launch(void* const* d_in, const int* in_sizes, int n_in,
                              void* d_out, int out_size) {
    const float* x   = (const float*)d_in[0];
    const int*   ei  = (const int*)  d_in[1];
    const float* W1l = (const float*)d_in[2];
    const float* b1l = (const float*)d_in[3];
    const float* W1r = (const float*)d_in[4];
    const float* W2l = (const float*)d_in[5];
    const float* b2l = (const float*)d_in[6];
    const float* W2r = (const float*)d_in[7];
    float* out = (float*)d_out;

    int n_nodes = in_sizes[0] / D;
    int n_edges = in_sizes[1] / 2;
    const int* src = ei;
    const int* dst = ei + n_edges;

    __half *mh, *ml, *xh, *xl, *w16;
    int *deg, *rowptr, *cursor, *csr, *bsums, *boffs;
    cudaGetSymbolAddress((void**)&mh,     g_meanh);
    cudaGetSymbolAddress((void**)&ml,     g_meanl);
    cudaGetSymbolAddress((void**)&xh,     g_xh);
    cudaGetSymbolAddress((void**)&xl,     g_xl);
    cudaGetSymbolAddress((void**)&w16,    g_w16);
    cudaGetSymbolAddress((void**)&deg,    g_deg);
    cudaGetSymbolAddress((void**)&rowptr, g_rowptr);
    cudaGetSymbolAddress((void**)&cursor, g_cursor);
    cudaGetSymbolAddress((void**)&csr,    g_csrsrc);
    cudaGetSymbolAddress((void**)&bsums,  g_blocksums);
    cudaGetSymbolAddress((void**)&boffs,  g_blockoffs);

    const int EPI_SMEM = 4 * 32 * EPI_LD * (int)sizeof(float);  // ~34.8 KB
    cudaFuncSetAttribute(combine_wmma,
                         cudaFuncAttributeMaxDynamicSharedMemorySize, EPI_SMEM);

    int eblocks = (n_edges + 255) / 256;
    int nscan = (n_nodes + 1023) / 1024;
    int nblocks = (n_nodes + 255) / 256;
    int npairs = (n_nodes + 1) / 2;
    int ablocks = (npairs * 32 + 255) / 256;
    int cblocks = (n_nodes + TILE - 1) / TILE;
    int n4 = n_nodes * D / 4;
    int vblocks = (n4 + 255) / 256;

    // ---- CSR build + conversions ----
    cudaMemsetAsync(deg, 0, (size_t)n_nodes * sizeof(int));
    convert_kernel<<<vblocks, 256>>>((const float4*)x, (uint2*)xh, (uint2*)xl, n4);
    wsplit_kernel<<<16, 256>>>(W1l, W1r, W2l, W2r, w16);
    count_kernel<<<eblocks, 256>>>(dst, deg, n_edges);
    scan_kernel<<<nscan, 1024>>>(deg, rowptr, bsums, n_nodes);
    scan_kernel<<<1, 1024>>>(bsums, boffs, nullptr, nscan);
    add_off_kernel<<<nblocks, 256>>>(rowptr, cursor, boffs, n_nodes);
    fill_kernel<<<eblocks, 256>>>(src, dst, cursor, csr, n_edges);

    // ---- Layer 1: mean of x -> h (emitted as hi/lo fp16 into xh/xl) ----
    aggregate_kernel<<<ablocks, 256>>>((const uint2*)xh, csr, rowptr, deg,
                                       mh, ml, n_nodes);
    combine_wmma<<<cblocks, 128, EPI_SMEM>>>(mh, ml, xh, xl,
                                             w16 + 0 * 4 * 4096, b1l,
                                             nullptr, xh, xl, n_nodes, 1);

    // ---- Layer 2: mean of h -> out (fp32) ----
    aggregate_kernel<<<ablocks, 256>>>((const uint2*)xh, csr, rowptr, deg,
                                       mh, ml, n_nodes);
    combine_wmma<<<cblocks, 128, EPI_SMEM>>>(mh, ml, xh, xl,
                                             w16 + 1 * 4 * 4096, b2l,
                                             out, nullptr, nullptr, n_nodes, 0);
}

// round 12
// speedup vs baseline: 1.0345x; 1.0345x over previous
#include <cuda_runtime.h>
#include <cuda_fp16.h>
#include <mma.h>
#include <cstdint>

using namespace nvcuda;

#define D 64
#define MAXN 100000
#define MAXNP 100096           // padded so last tile's wmma A-loads stay in-bounds
#define MAXE 1600000
#define TILE 128
#define EPI_LD 68              // epilogue smem row stride (floats)

// ---------------- static scratch (no allocation allowed) -------------------
__device__ __half g_meanh[(size_t)MAXNP * D];
__device__ __half g_meanl[(size_t)MAXNP * D];
__device__ __half g_xh[(size_t)MAXNP * D];    // hi of gather/self operand
__device__ __half g_xl[(size_t)MAXNP * D];    // lo residual
__device__ __half g_w16[2 * 4 * 4096];        // per layer: wl_hi, wl_lo, wr_hi, wr_lo
__device__ int    g_deg[MAXN];                // zero at load; re-zeroed by agg L2
__device__ int    g_rowptr[MAXN];
__device__ int    g_cursor[MAXN];
__device__ int    g_csrsrc[MAXE + 8];         // +8: unpredicated batch idx loads
__device__ int    g_blocksums[128];

// ---------------- fused convert(x -> hi/lo fp16) + degree count -------------
__global__ void convcount_kernel(const float4* __restrict__ in,
                                 uint2* __restrict__ outh,
                                 uint2* __restrict__ outl, int n4,
                                 const int* __restrict__ dst,
                                 int* __restrict__ deg, int n_edges) {
    int i = blockIdx.x * blockDim.x + threadIdx.x;
    if (i < n4) {
        float4 v = __ldg(in + i);
        __half2 h0 = __floats2half2_rn(v.x, v.y);
        __half2 h1 = __floats2half2_rn(v.z, v.w);
        float2 f0 = __half22float2(h0);
        float2 f1 = __half22float2(h1);
        __half2 l0 = __floats2half2_rn(v.x - f0.x, v.y - f0.y);
        __half2 l1 = __floats2half2_rn(v.z - f1.x, v.w - f1.y);
        outh[i] = make_uint2(*(unsigned*)&h0, *(unsigned*)&h1);
        outl[i] = make_uint2(*(unsigned*)&l0, *(unsigned*)&l1);
    }
    if (i < n_edges) atomicAdd(deg + __ldg(dst + i), 1);
}

// ---------------- CSR build --------------------------------------------------
__global__ void scan_kernel(const int* __restrict__ in, int* __restrict__ out,
                            int* sums, int n) {
    __shared__ int sm[1024];
    int t = threadIdx.x;
    int i = blockIdx.x * 1024 + t;
    int v = (i < n) ? in[i] : 0;
    sm[t] = v;
    __syncthreads();
#pragma unroll
    for (int off = 1; off < 1024; off <<= 1) {
        int add = (t >= off) ? sm[t - off] : 0;
        __syncthreads();
        sm[t] += add;
        __syncthreads();
    }
    if (i < n) out[i] = sm[t] - v;
    if (sums != nullptr && t == 1023) sums[blockIdx.x] = sm[1023];
}

// Fused: scan the (<=128) chunk sums in smem, then add offsets.
__global__ void add_off_kernel(int* __restrict__ rowptr, int* __restrict__ cursor,
                               const int* __restrict__ bsums, int nscan, int n) {
    __shared__ int sb[128];
    __shared__ int sorig[128];
    int t = threadIdx.x;
    if (t < 128) {
        int v = (t < nscan) ? bsums[t] : 0;
        sb[t] = v;
        sorig[t] = v;
    }
    __syncthreads();
#pragma unroll
    for (int off = 1; off < 128; off <<= 1) {
        int add = 0;
        if (t < 128 && t >= off) add = sb[t - off];
        __syncthreads();
        if (t < 128) sb[t] += add;
        __syncthreads();
    }
    int i = blockIdx.x * blockDim.x + t;
    if (i < n) {
        int c = i >> 10;
        int v = rowptr[i] + sb[c] - sorig[c];
        rowptr[i] = v;
        cursor[i] = v;
    }
}

__global__ void fill_kernel(const int* __restrict__ src, const int* __restrict__ dst,
                            int* __restrict__ cursor, int* __restrict__ csr,
                            int n_edges) {
    int e = blockIdx.x * blockDim.x + threadIdx.x;
    if (e < n_edges) {
        int d = __ldg(dst + e);
        int pos = atomicAdd(cursor + d, 1);
        csr[pos] = __ldg(src + e);
    }
}

// ---------------- weight hi/lo split (both layers) ---------------------------
__global__ void wsplit_kernel(const float* __restrict__ W1l,
                              const float* __restrict__ W1r,
                              const float* __restrict__ W2l,
                              const float* __restrict__ W2r,
                              __half* __restrict__ w16) {
    int i = blockIdx.x * blockDim.x + threadIdx.x;
    if (i >= 4096) return;
    const float* srcs[4] = {W1l, W1r, W2l, W2r};
#pragma unroll
    for (int l = 0; l < 2; l++) {
#pragma unroll
        for (int m = 0; m < 2; m++) {
            float v = __ldg(srcs[l * 2 + m] + i);
            __half hi = __float2half_rn(v);
            __half lo = __float2half_rn(v - __half2float(hi));
            w16[((size_t)l * 4 + m * 2 + 0) * 4096 + i] = hi;
            w16[((size_t)l * 4 + m * 2 + 1) * 4096 + i] = lo;
        }
    }
}

// ---------------- aggregate: fp16 gather, hi/lo mean out ---------------------
// 2 nodes/warp. zero_deg: last consumer of deg this call resets it to 0 so
// the next (graph-replayed) call sees a zeroed counter array.
__global__ void aggregate_kernel(const uint2* __restrict__ xh2,
                                 const int* __restrict__ csr,
                                 const int* __restrict__ rowptr,
                                 int* __restrict__ deg,
                                 __half* __restrict__ mh,
                                 __half* __restrict__ ml,
                                 int n_nodes, int zero_deg) {
    int warp = (blockIdx.x * blockDim.x + threadIdx.x) >> 5;
    int n0 = warp * 2;
    if (n0 >= n_nodes) return;
    int lane = threadIdx.x & 31;
    int half_ = lane >> 4;
    int q = lane & 15;
    int node = n0 + half_;
    bool valid = node < n_nodes;

    int base = valid ? __ldg((const int*)rowptr + node) : 0;
    int dg   = valid ? __ldg((const int*)deg + node) : 0;
    if (zero_deg && valid && q == 0) deg[node] = 0;
    int dgA = __shfl_sync(0xffffffffu, dg, 0);
    int dgB = __shfl_sync(0xffffffffu, dg, 16);
    int maxdg = max(dgA, dgB);

    float a0 = 0.f, a1 = 0.f, a2 = 0.f, a3 = 0.f;

    for (int j = 0; j < maxdg; j += 8) {
        int idx[8];
#pragma unroll
        for (int i = 0; i < 8; i++)
            idx[i] = __ldg(csr + base + j + i);      // padded: always in-bounds
#pragma unroll
        for (int i = 0; i < 8; i++) {
            if (j + i < dg) {
                uint2 v = __ldg(xh2 + (size_t)idx[i] * 16 + q);
                float2 f0 = __half22float2(*(__half2*)&v.x);
                float2 f1 = __half22float2(*(__half2*)&v.y);
                a0 += f0.x; a1 += f0.y; a2 += f1.x; a3 += f1.y;
            }
        }
    }

    float inv = 1.0f / fmaxf((float)dg, 1.0f);
    a0 *= inv; a1 *= inv; a2 *= inv; a3 *= inv;
    if (valid) {
        __half2 h0 = __floats2half2_rn(a0, a1);
        __half2 h1 = __floats2half2_rn(a2, a3);
        float2 f0 = __half22float2(h0);
        float2 f1 = __half22float2(h1);
        __half2 l0 = __floats2half2_rn(a0 - f0.x, a1 - f0.y);
        __half2 l1 = __floats2half2_rn(a2 - f1.x, a3 - f1.y);
        *(uint2*)(mh + (size_t)node * D + q * 4) =
            make_uint2(*(unsigned*)&h0, *(unsigned*)&h1);
        *(uint2*)(ml + (size_t)node * D + q * 4) =
            make_uint2(*(unsigned*)&l0, *(unsigned*)&l1);
    }
}

// ---------------- combine via wmma HMMA (R10 version) ------------------------
__global__ void __launch_bounds__(128)
combine_wmma(const __half* __restrict__ mh, const __half* __restrict__ ml,
             const __half* __restrict__ ah, const __half* __restrict__ al,
             const __half* __restrict__ w,     // wl_hi, wl_lo, wr_hi, wr_lo
             const float* __restrict__ bias,
             float* __restrict__ out32,        // layer 2 final (or null)
             __half* __restrict__ oh,          // layer 1 hi out (or null)
             __half* __restrict__ ol,          // layer 1 lo out (or null)
             int n_nodes, int do_relu) {
    extern __shared__ float epi[];            // [4][32][EPI_LD]
    int tid = threadIdx.x, wid = tid >> 5, lane = tid & 31;
    int rbase = blockIdx.x * TILE + wid * 32;

    wmma::fragment<wmma::accumulator, 16, 16, 16, float> acc[2][4];
#pragma unroll
    for (int mt = 0; mt < 2; mt++)
#pragma unroll
        for (int nt = 0; nt < 4; nt++) wmma::fill_fragment(acc[mt][nt], 0.0f);

#pragma unroll
    for (int k = 0; k < D; k += 16) {
        wmma::fragment<wmma::matrix_a, 16, 16, 16, __half, wmma::row_major>
            fmh[2], fml[2], fah[2], fal[2];
#pragma unroll
        for (int mt = 0; mt < 2; mt++) {
            size_t ab = (size_t)(rbase + mt * 16) * D + k;
            wmma::load_matrix_sync(fmh[mt], mh + ab, D);
            wmma::load_matrix_sync(fml[mt], ml + ab, D);
            wmma::load_matrix_sync(fah[mt], ah + ab, D);
            wmma::load_matrix_sync(fal[mt], al + ab, D);
        }
#pragma unroll
        for (int nt = 0; nt < 4; nt++) {
            size_t wb = (size_t)(nt * 16) * D + k;
            wmma::fragment<wmma::matrix_b, 16, 16, 16, __half, wmma::col_major>
                bwlh, bwll, bwrh, bwrl;
            wmma::load_matrix_sync(bwlh, w + 0 * 4096 + wb, D);
            wmma::load_matrix_sync(bwll, w + 1 * 4096 + wb, D);
            wmma::load_matrix_sync(bwrh, w + 2 * 4096 + wb, D);
            wmma::load_matrix_sync(bwrl, w + 3 * 4096 + wb, D);
#pragma unroll
            for (int mt = 0; mt < 2; mt++) {
                wmma::mma_sync(acc[mt][nt], fmh[mt], bwlh, acc[mt][nt]);
                wmma::mma_sync(acc[mt][nt], fml[mt], bwlh, acc[mt][nt]);
                wmma::mma_sync(acc[mt][nt], fmh[mt], bwll, acc[mt][nt]);
                wmma::mma_sync(acc[mt][nt], fah[mt], bwrh, acc[mt][nt]);
                wmma::mma_sync(acc[mt][nt], fal[mt], bwrh, acc[mt][nt]);
                wmma::mma_sync(acc[mt][nt], fah[mt], bwrl, acc[mt][nt]);
            }
        }
    }

    // epilogue: acc -> smem -> bias + relu -> coalesced stores
    float* ws = epi + (size_t)wid * 32 * EPI_LD;
#pragma unroll
    for (int mt = 0; mt < 2; mt++)
#pragma unroll
        for (int nt = 0; nt < 4; nt++)
            wmma::store_matrix_sync(ws + mt * 16 * EPI_LD + nt * 16,
                                    acc[mt][nt], EPI_LD, wmma::mem_row_major);
    __syncwarp();

    int q = lane & 15;
    int rh = lane >> 4;
    float4 b4 = __ldg((const float4*)bias + q);
#pragma unroll
    for (int it = 0; it < 16; it++) {
        int r = it * 2 + rh;
        float4 v = *(float4*)(ws + r * EPI_LD + q * 4);
        v.x += b4.x; v.y += b4.y; v.z += b4.z; v.w += b4.w;
        if (do_relu) {
            v.x = fmaxf(v.x, 0.f); v.y = fmaxf(v.y, 0.f);
            v.z = fmaxf(v.z, 0.f); v.w = fmaxf(v.w, 0.f);
        }
        int gm = rbase + r;
        if (gm < n_nodes) {
            if (out32) *(float4*)(out32 + (size_t)gm * D + q * 4) = v;
            if (oh) {
                __half2 h0 = __floats2half2_rn(v.x, v.y);
                __half2 h1 = __floats2half2_rn(v.z, v.w);
                float2 f0 = __half22float2(h0);
                float2 f1 = __half22float2(h1);
                __half2 l0 = __floats2half2_rn(v.x - f0.x, v.y - f0.y);
                __half2 l1 = __floats2half2_rn(v.z - f1.x, v.w - f1.y);
                *(uint2*)(oh + (size_t)gm * D + q * 4) =
                    make_uint2(*(unsigned*)&h0, *(unsigned*)&h1);
                *(uint2*)(ol + (size_t)gm * D + q * 4) =
                    make_uint2(*(unsigned*)&l0, *(unsigned*)&l1);
            }
        }
    }
}

// ---------------------------------------------------------------------------
extern "C" void kernel_launch(void* const* d_in, const int* in_sizes, int n_in,
                              void* d_out, int out_size) {
    const float* x   = (const float*)d_in[0];
    const int*   ei  = (const int*)  d_in[1];
    const float* W1l = (const float*)d_in[2];
    const float* b1l = (const float*)d_in[3];
    const float* W1r = (const float*)d_in[4];
    const float* W2l = (const float*)d_in[5];
    const float* b2l = (const float*)d_in[6];
    const float* W2r = (const float*)d_in[7];
    float* out = (float*)d_out;

    int n_nodes = in_sizes[0] / D;
    int n_edges = in_sizes[1] / 2;
    const int* src = ei;
    const int* dst = ei + n_edges;

    __half *mh, *ml, *xh, *xl, *w16;
    int *deg, *rowptr, *cursor, *csr, *bsums;
    cudaGetSymbolAddress((void**)&mh,     g_meanh);
    cudaGetSymbolAddress((void**)&ml,     g_meanl);
    cudaGetSymbolAddress((void**)&xh,     g_xh);
    cudaGetSymbolAddress((void**)&xl,     g_xl);
    cudaGetSymbolAddress((void**)&w16,    g_w16);
    cudaGetSymbolAddress((void**)&deg,    g_deg);
    cudaGetSymbolAddress((void**)&rowptr, g_rowptr);
    cudaGetSymbolAddress((void**)&cursor, g_cursor);
    cudaGetSymbolAddress((void**)&csr,    g_csrsrc);
    cudaGetSymbolAddress((void**)&bsums,  g_blocksums);

    const int EPI_SMEM = 4 * 32 * EPI_LD * (int)sizeof(float);  // ~34.8 KB
    cudaFuncSetAttribute(combine_wmma,
                         cudaFuncAttributeMaxDynamicSharedMemorySize, EPI_SMEM);

    int n4 = n_nodes * D / 4;
    int ccblocks = ((n4 > n_edges ? n4 : n_edges) + 255) / 256;
    int eblocks = (n_edges + 255) / 256;
    int nscan = (n_nodes + 1023) / 1024;
    int nblocks = (n_nodes + 255) / 256;
    int npairs = (n_nodes + 1) / 2;
    int ablocks = (npairs * 32 + 255) / 256;
    int cblocks = (n_nodes + TILE - 1) / TILE;

    // ---- CSR build (deg enters zeroed; re-zeroed by aggregate L2) ----
    convcount_kernel<<<ccblocks, 256>>>((const float4*)x, (uint2*)xh, (uint2*)xl,
                                        n4, dst, deg, n_edges);        // #1
    scan_kernel<<<nscan, 1024>>>(deg, rowptr, bsums, n_nodes);         // #2
    add_off_kernel<<<nblocks, 256>>>(rowptr, cursor, bsums, nscan,
                                     n_nodes);                         // #3
    fill_kernel<<<eblocks, 256>>>(src, dst, cursor, csr, n_edges);     // #4

    // ---- Layer 1 ----
    aggregate_kernel<<<ablocks, 256>>>((const uint2*)xh, csr, rowptr, deg,
                                       mh, ml, n_nodes, 0);            // #5 (ncu)
    wsplit_kernel<<<16, 256>>>(W1l, W1r, W2l, W2r, w16);               // #6
    combine_wmma<<<cblocks, 128, EPI_SMEM>>>(mh, ml, xh, xl,
                                             w16 + 0 * 4 * 4096, b1l,
                                             nullptr, xh, xl, n_nodes, 1);

    // ---- Layer 2 (aggregate also re-zeroes deg for the next call) ----
    aggregate_kernel<<<ablocks, 256>>>((const uint2*)xh, csr, rowptr, deg,
                                       mh, ml, n_nodes, 1);
    combine_wmma<<<cblocks, 128, EPI_SMEM>>>(mh, ml, xh, xl,
                                             w16 + 1 * 4 * 4096, b2l,
                                             out, nullptr, nullptr, n_nodes, 0);
}